// round 1
// baseline (speedup 1.0000x reference)
#include <cuda_runtime.h>

#define N_NODES 100000
#define N_EDGES 50000
#define NNZ     800000
#define C       256
#define C4      (C / 4)   // 64 float4 per row

// Scratch for m_{1->0} (node aggregation). Static __device__ array (allowed scratch).
__device__ float g_m[(size_t)N_NODES * C];

// ---------------------------------------------------------------------------
// Zero x_1 (in d_out) and g_m scratch
// ---------------------------------------------------------------------------
__global__ void zero_kernel(float4* __restrict__ x1) {
    int idx = blockIdx.x * blockDim.x + threadIdx.x;
    int stride = gridDim.x * blockDim.x;
    float4 z = make_float4(0.f, 0.f, 0.f, 0.f);
    float4* m4 = reinterpret_cast<float4*>(g_m);
    for (int i = idx; i < N_EDGES * C4; i += stride) x1[i] = z;
    for (int i = idx; i < N_NODES * C4; i += stride) m4[i] = z;
}

// ---------------------------------------------------------------------------
// Phase B: x_1[e] += x_0[n]  for each incidence (n, e)
// One 64-lane group per incidence; each lane owns one float4 (4 channels).
// ---------------------------------------------------------------------------
__global__ void scatter_v2e(const float4* __restrict__ x0,
                            const int* __restrict__ node_idx,
                            const int* __restrict__ edge_idx,
                            float4* __restrict__ x1) {
    long long gid = (long long)blockIdx.x * blockDim.x + threadIdx.x;
    int i  = (int)(gid >> 6);
    int c4 = (int)(gid & 63);
    if (i >= NNZ) return;
    int n = node_idx[i];
    int e = edge_idx[i];
    float4 v = x0[(long long)n * C4 + c4];
    atomicAdd(&x1[(long long)e * C4 + c4], v);
}

// ---------------------------------------------------------------------------
// Phase C: m[n] += x_1[e]  for each incidence (n, e)
// ---------------------------------------------------------------------------
__global__ void scatter_e2v(const float4* __restrict__ x1,
                            const int* __restrict__ node_idx,
                            const int* __restrict__ edge_idx) {
    long long gid = (long long)blockIdx.x * blockDim.x + threadIdx.x;
    int i  = (int)(gid >> 6);
    int c4 = (int)(gid & 63);
    if (i >= NNZ) return;
    int n = node_idx[i];
    int e = edge_idx[i];
    float4 v = x1[(long long)e * C4 + c4];
    float4* m4 = reinterpret_cast<float4*>(g_m);
    atomicAdd(&m4[(long long)n * C4 + c4], v);
}

// ---------------------------------------------------------------------------
// Phase D: out0 = (x_0 + m) @ W^T + b
// Classic 128x128x8 register-tiled SGEMM, 256 threads, 8x8 per thread.
// out0[m][n] = sum_k (x0[m][k] + g_m[m][k]) * W[n][k] + b[n]
// ---------------------------------------------------------------------------
#define BM 128
#define BN 128
#define BK 8
#define TM 8
#define TN 8

__global__ __launch_bounds__(256)
void gin_gemm(const float* __restrict__ x0,
              const float* __restrict__ W,
              const float* __restrict__ bias,
              float* __restrict__ out) {
    __shared__ float As[BK][BM];
    __shared__ float Bs[BK][BN];

    int m0 = blockIdx.x * BM;
    int n0 = blockIdx.y * BN;
    int tid = threadIdx.x;

    // Load mapping: row = tid/2 (0..127), col4 = (tid&1)*4 within BK=8
    int l_row  = tid >> 1;
    int l_col  = (tid & 1) * 4;

    // Compute mapping: 16x16 thread grid, each 8x8 outputs
    int tr = (tid >> 4) * TM;   // row offset within tile
    int tc = (tid & 15) * TN;   // col offset within tile

    float acc[TM][TN];
    #pragma unroll
    for (int i = 0; i < TM; i++)
        #pragma unroll
        for (int j = 0; j < TN; j++)
            acc[i][j] = 0.f;

    for (int k0 = 0; k0 < C; k0 += BK) {
        // --- Load A tile (x0 + g_m), transposed into As[k][m] ---
        {
            int gm = m0 + l_row;
            float4 av = make_float4(0.f, 0.f, 0.f, 0.f);
            if (gm < N_NODES) {
                const float4* xrow = reinterpret_cast<const float4*>(&x0[(size_t)gm * C + k0 + l_col]);
                const float4* mrow = reinterpret_cast<const float4*>(&g_m[(size_t)gm * C + k0 + l_col]);
                float4 xv = *xrow;
                float4 mv = *mrow;
                av.x = xv.x + mv.x;
                av.y = xv.y + mv.y;
                av.z = xv.z + mv.z;
                av.w = xv.w + mv.w;
            }
            As[l_col + 0][l_row] = av.x;
            As[l_col + 1][l_row] = av.y;
            As[l_col + 2][l_row] = av.z;
            As[l_col + 3][l_row] = av.w;
        }
        // --- Load B tile: Bs[k][n] = W[n0+n][k0+k] ---
        {
            int gn = n0 + l_row;   // N = 256, grid covers exactly, no guard needed
            const float4* wrow = reinterpret_cast<const float4*>(&W[(size_t)gn * C + k0 + l_col]);
            float4 wv = *wrow;
            Bs[l_col + 0][l_row] = wv.x;
            Bs[l_col + 1][l_row] = wv.y;
            Bs[l_col + 2][l_row] = wv.z;
            Bs[l_col + 3][l_row] = wv.w;
        }
        __syncthreads();

        #pragma unroll
        for (int k = 0; k < BK; k++) {
            float ra[TM], rb[TN];
            #pragma unroll
            for (int i = 0; i < TM; i++) ra[i] = As[k][tr + i];
            #pragma unroll
            for (int j = 0; j < TN; j++) rb[j] = Bs[k][tc + j];
            #pragma unroll
            for (int i = 0; i < TM; i++)
                #pragma unroll
                for (int j = 0; j < TN; j++)
                    acc[i][j] = fmaf(ra[i], rb[j], acc[i][j]);
        }
        __syncthreads();
    }

    // --- Epilogue: add bias, write out ---
    float bj[TN];
    #pragma unroll
    for (int j = 0; j < TN; j++) bj[j] = bias[n0 + tc + j];

    #pragma unroll
    for (int i = 0; i < TM; i++) {
        int gm = m0 + tr + i;
        if (gm < N_NODES) {
            #pragma unroll
            for (int j4 = 0; j4 < TN; j4 += 4) {
                float4 v;
                v.x = acc[i][j4 + 0] + bj[j4 + 0];
                v.y = acc[i][j4 + 1] + bj[j4 + 1];
                v.z = acc[i][j4 + 2] + bj[j4 + 2];
                v.w = acc[i][j4 + 3] + bj[j4 + 3];
                *reinterpret_cast<float4*>(&out[(size_t)gm * C + n0 + tc + j4]) = v;
            }
        }
    }
}

// ---------------------------------------------------------------------------
// Launch
// ---------------------------------------------------------------------------
extern "C" void kernel_launch(void* const* d_in, const int* in_sizes, int n_in,
                              void* d_out, int out_size) {
    const float* x0       = (const float*)d_in[0];
    const int*   node_idx = (const int*)d_in[1];
    const int*   edge_idx = (const int*)d_in[2];
    const float* W        = (const float*)d_in[3];
    const float* b        = (const float*)d_in[4];

    float* out = (float*)d_out;
    float* x1  = out + (size_t)N_NODES * C;   // second tuple element region

    // 1. zero x_1 and g_m
    zero_kernel<<<4096, 256>>>(reinterpret_cast<float4*>(x1));

    // 2. vertex -> edge scatter: x_1[e] += x_0[n]
    {
        long long total = (long long)NNZ * C4;          // 51.2M threads
        int blocks = (int)((total + 255) / 256);
        scatter_v2e<<<blocks, 256>>>(reinterpret_cast<const float4*>(x0),
                                     node_idx, edge_idx,
                                     reinterpret_cast<float4*>(x1));
    }

    // 3. edge -> vertex scatter: m[n] += x_1[e]
    {
        long long total = (long long)NNZ * C4;
        int blocks = (int)((total + 255) / 256);
        scatter_e2v<<<blocks, 256>>>(reinterpret_cast<const float4*>(x1),
                                     node_idx, edge_idx);
    }

    // 4. out0 = (x_0 + m) @ W^T + b
    {
        dim3 grid((N_NODES + BM - 1) / BM, C / BN);     // 782 x 2
        gin_gemm<<<grid, 256>>>(x0, W, b, out);
    }
}

// round 2
// speedup vs baseline: 1.3059x; 1.3059x over previous
#include <cuda_runtime.h>
#include <cstdint>

#define N_NODES 100000
#define N_EDGES 50000
#define NNZ     800000
#define C       256
#define C4      (C / 4)   // 64 float4 per row

// Scratch for m_{1->0} (node aggregation). Static __device__ array (allowed scratch).
__device__ float g_m[(size_t)N_NODES * C];

// ---------------------------------------------------------------------------
// Zero x_1 (in d_out) and g_m scratch
// ---------------------------------------------------------------------------
__global__ void zero_kernel(float4* __restrict__ x1) {
    int idx = blockIdx.x * blockDim.x + threadIdx.x;
    int stride = gridDim.x * blockDim.x;
    float4 z = make_float4(0.f, 0.f, 0.f, 0.f);
    float4* m4 = reinterpret_cast<float4*>(g_m);
    for (int i = idx; i < N_EDGES * C4; i += stride) x1[i] = z;
    for (int i = idx; i < N_NODES * C4; i += stride) m4[i] = z;
}

// ---------------------------------------------------------------------------
// Phase B: x_1[e] += x_0[n]  for each incidence (n, e)
// ---------------------------------------------------------------------------
__global__ void scatter_v2e(const float4* __restrict__ x0,
                            const int* __restrict__ node_idx,
                            const int* __restrict__ edge_idx,
                            float4* __restrict__ x1) {
    long long gid = (long long)blockIdx.x * blockDim.x + threadIdx.x;
    int i  = (int)(gid >> 6);
    int c4 = (int)(gid & 63);
    if (i >= NNZ) return;
    int n = node_idx[i];
    int e = edge_idx[i];
    float4 v = x0[(long long)n * C4 + c4];
    atomicAdd(&x1[(long long)e * C4 + c4], v);
}

// ---------------------------------------------------------------------------
// Phase C: m[n] += x_1[e]  for each incidence (n, e)
// ---------------------------------------------------------------------------
__global__ void scatter_e2v(const float4* __restrict__ x1,
                            const int* __restrict__ node_idx,
                            const int* __restrict__ edge_idx) {
    long long gid = (long long)blockIdx.x * blockDim.x + threadIdx.x;
    int i  = (int)(gid >> 6);
    int c4 = (int)(gid & 63);
    if (i >= NNZ) return;
    int n = node_idx[i];
    int e = edge_idx[i];
    float4 v = x1[(long long)e * C4 + c4];
    float4* m4 = reinterpret_cast<float4*>(g_m);
    atomicAdd(&m4[(long long)n * C4 + c4], v);
}

// ---------------------------------------------------------------------------
// Phase D: out0 = (x_0 + g_m) @ W^T + b   via TF32 mma.sync tensor cores.
// BM=64, BN=256 (full N in one block -> A read exactly once), BK=16.
// 256 threads = 8 warps in 2(M) x 4(N); warp tile 32x64 = 2 x 8 m16n8k8 frags.
// ---------------------------------------------------------------------------
#define GBM 64
#define GBN 256
#define GBK 16
#define SPAD 20   // smem row stride in words (conflict-free for r*20+c pattern)

__device__ __forceinline__ uint32_t f2tf32(float f) {
    uint32_t r;
    asm("cvt.rna.tf32.f32 %0, %1;" : "=r"(r) : "f"(f));
    return r;
}

__device__ __forceinline__ void mma_tf32(float c[4], const uint32_t a[4], const uint32_t b[2]) {
    asm volatile(
        "mma.sync.aligned.m16n8k8.row.col.f32.tf32.tf32.f32 "
        "{%0,%1,%2,%3}, {%4,%5,%6,%7}, {%8,%9}, {%0,%1,%2,%3};\n"
        : "+f"(c[0]), "+f"(c[1]), "+f"(c[2]), "+f"(c[3])
        : "r"(a[0]), "r"(a[1]), "r"(a[2]), "r"(a[3]), "r"(b[0]), "r"(b[1]));
}

__global__ __launch_bounds__(256)
void gin_gemm_tf32(const float* __restrict__ x0,
                   const float* __restrict__ W,
                   const float* __restrict__ bias,
                   float* __restrict__ out) {
    __shared__ uint32_t As[GBM][SPAD];   // [m][k] tf32
    __shared__ uint32_t Bs[GBN][SPAD];   // [n][k] tf32

    const int tid  = threadIdx.x;
    const int lane = tid & 31;
    const int wid  = tid >> 5;
    const int m_off = (wid >> 2) * 32;   // 0 or 32
    const int n_off = (wid & 3) * 64;    // 0,64,128,192
    const int m0 = blockIdx.x * GBM;

    // A load mapping: 64 rows x 4 float4 groups = 256 threads
    const int a_row = tid >> 2;                 // 0..63
    const int a_col = (tid & 3) * 4;            // 0,4,8,12
    const int  a_gm  = m0 + a_row;
    const bool a_ok  = a_gm < N_NODES;
    const size_t a_base = (size_t)a_gm * C + a_col;

    // B load mapping: rows tid>>1 and tid>>1+128, cols (tid&1)*8 .. +7
    const int b_row = tid >> 1;                 // 0..127
    const int b_col = (tid & 1) * 8;            // 0 or 8
    const size_t b_base = (size_t)b_row * C + b_col;

    float acc[2][8][4];
    #pragma unroll
    for (int mf = 0; mf < 2; mf++)
        #pragma unroll
        for (int nf = 0; nf < 8; nf++)
            #pragma unroll
            for (int q = 0; q < 4; q++)
                acc[mf][nf][q] = 0.f;

    // ---- prefetch tile 0 ----
    float4 pa;
    float4 pb0, pb1, pb2, pb3;
    {
        if (a_ok) {
            float4 xv = *reinterpret_cast<const float4*>(&x0[a_base]);
            float4 mv = *reinterpret_cast<const float4*>(&g_m[a_base]);
            pa = make_float4(xv.x + mv.x, xv.y + mv.y, xv.z + mv.z, xv.w + mv.w);
        } else {
            pa = make_float4(0.f, 0.f, 0.f, 0.f);
        }
        pb0 = *reinterpret_cast<const float4*>(&W[b_base + 0]);
        pb1 = *reinterpret_cast<const float4*>(&W[b_base + 4]);
        pb2 = *reinterpret_cast<const float4*>(&W[b_base + (size_t)128 * C + 0]);
        pb3 = *reinterpret_cast<const float4*>(&W[b_base + (size_t)128 * C + 4]);
    }

    const int r = lane >> 2;   // 0..7
    const int cq = lane & 3;   // 0..3

    for (int t = 0; t < C / GBK; t++) {
        // ---- stage prefetched tile into smem (convert to tf32) ----
        As[a_row][a_col + 0] = f2tf32(pa.x);
        As[a_row][a_col + 1] = f2tf32(pa.y);
        As[a_row][a_col + 2] = f2tf32(pa.z);
        As[a_row][a_col + 3] = f2tf32(pa.w);

        Bs[b_row][b_col + 0] = f2tf32(pb0.x);
        Bs[b_row][b_col + 1] = f2tf32(pb0.y);
        Bs[b_row][b_col + 2] = f2tf32(pb0.z);
        Bs[b_row][b_col + 3] = f2tf32(pb0.w);
        Bs[b_row][b_col + 4] = f2tf32(pb1.x);
        Bs[b_row][b_col + 5] = f2tf32(pb1.y);
        Bs[b_row][b_col + 6] = f2tf32(pb1.z);
        Bs[b_row][b_col + 7] = f2tf32(pb1.w);
        Bs[b_row + 128][b_col + 0] = f2tf32(pb2.x);
        Bs[b_row + 128][b_col + 1] = f2tf32(pb2.y);
        Bs[b_row + 128][b_col + 2] = f2tf32(pb2.z);
        Bs[b_row + 128][b_col + 3] = f2tf32(pb2.w);
        Bs[b_row + 128][b_col + 4] = f2tf32(pb3.x);
        Bs[b_row + 128][b_col + 5] = f2tf32(pb3.y);
        Bs[b_row + 128][b_col + 6] = f2tf32(pb3.z);
        Bs[b_row + 128][b_col + 7] = f2tf32(pb3.w);
        __syncthreads();

        // ---- prefetch next tile ----
        if (t + 1 < C / GBK) {
            int k0 = (t + 1) * GBK;
            if (a_ok) {
                float4 xv = *reinterpret_cast<const float4*>(&x0[a_base + k0]);
                float4 mv = *reinterpret_cast<const float4*>(&g_m[a_base + k0]);
                pa = make_float4(xv.x + mv.x, xv.y + mv.y, xv.z + mv.z, xv.w + mv.w);
            }
            pb0 = *reinterpret_cast<const float4*>(&W[b_base + k0 + 0]);
            pb1 = *reinterpret_cast<const float4*>(&W[b_base + k0 + 4]);
            pb2 = *reinterpret_cast<const float4*>(&W[b_base + (size_t)128 * C + k0 + 0]);
            pb3 = *reinterpret_cast<const float4*>(&W[b_base + (size_t)128 * C + k0 + 4]);
        }

        // ---- compute: 2 k-steps of m16n8k8 ----
        #pragma unroll
        for (int ks = 0; ks < 2; ks++) {
            const int kk = ks * 8;
            uint32_t aF[2][4];
            #pragma unroll
            for (int mf = 0; mf < 2; mf++) {
                int row = m_off + mf * 16 + r;
                aF[mf][0] = As[row][kk + cq];
                aF[mf][1] = As[row + 8][kk + cq];
                aF[mf][2] = As[row][kk + cq + 4];
                aF[mf][3] = As[row + 8][kk + cq + 4];
            }
            #pragma unroll
            for (int nf = 0; nf < 8; nf++) {
                uint32_t bF[2];
                int col = n_off + nf * 8 + r;
                bF[0] = Bs[col][kk + cq];
                bF[1] = Bs[col][kk + cq + 4];
                mma_tf32(acc[0][nf], aF[0], bF);
                mma_tf32(acc[1][nf], aF[1], bF);
            }
        }
        __syncthreads();
    }

    // ---- epilogue: add bias, write float2 per fragment-row ----
    #pragma unroll
    for (int mf = 0; mf < 2; mf++) {
        #pragma unroll
        for (int nf = 0; nf < 8; nf++) {
            int gc = n_off + nf * 8 + cq * 2;
            float bb0 = bias[gc];
            float bb1 = bias[gc + 1];
            int gr = m0 + m_off + mf * 16 + r;
            if (gr < N_NODES) {
                float2 v = make_float2(acc[mf][nf][0] + bb0, acc[mf][nf][1] + bb1);
                *reinterpret_cast<float2*>(&out[(size_t)gr * C + gc]) = v;
            }
            if (gr + 8 < N_NODES) {
                float2 v = make_float2(acc[mf][nf][2] + bb0, acc[mf][nf][3] + bb1);
                *reinterpret_cast<float2*>(&out[(size_t)(gr + 8) * C + gc]) = v;
            }
        }
    }
}

// ---------------------------------------------------------------------------
// Launch
// ---------------------------------------------------------------------------
extern "C" void kernel_launch(void* const* d_in, const int* in_sizes, int n_in,
                              void* d_out, int out_size) {
    const float* x0       = (const float*)d_in[0];
    const int*   node_idx = (const int*)d_in[1];
    const int*   edge_idx = (const int*)d_in[2];
    const float* W        = (const float*)d_in[3];
    const float* b        = (const float*)d_in[4];

    float* out = (float*)d_out;
    float* x1  = out + (size_t)N_NODES * C;   // second tuple element region

    // 1. zero x_1 and g_m
    zero_kernel<<<4096, 256>>>(reinterpret_cast<float4*>(x1));

    // 2. vertex -> edge scatter: x_1[e] += x_0[n]
    {
        long long total = (long long)NNZ * C4;
        int blocks = (int)((total + 255) / 256);
        scatter_v2e<<<blocks, 256>>>(reinterpret_cast<const float4*>(x0),
                                     node_idx, edge_idx,
                                     reinterpret_cast<float4*>(x1));
    }

    // 3. edge -> vertex scatter: m[n] += x_1[e]
    {
        long long total = (long long)NNZ * C4;
        int blocks = (int)((total + 255) / 256);
        scatter_e2v<<<blocks, 256>>>(reinterpret_cast<const float4*>(x1),
                                     node_idx, edge_idx);
    }

    // 4. out0 = (x_0 + g_m) @ W^T + b  (TF32 tensor cores)
    {
        int grid = (N_NODES + GBM - 1) / GBM;   // 1563
        gin_gemm_tf32<<<grid, 256>>>(x0, W, b, out);
    }
}

// round 3
// speedup vs baseline: 1.9767x; 1.5137x over previous
#include <cuda_runtime.h>
#include <cstdint>

#define N_NODES 100000
#define N_EDGES 50000
#define NNZ     800000
#define C       256
#define C4      (C / 4)   // 64 float4 per row

// ---------------- scratch (__device__ globals: allowed) ----------------
__device__ float g_m[(size_t)N_NODES * C];     // fused (x0 + m) for GEMM A
__device__ int   d_cnt_e[N_EDGES];
__device__ int   d_cnt_n[N_NODES];
__device__ int   d_off_e[N_EDGES + 1];
__device__ int   d_off_n[N_NODES + 1];
__device__ int   d_memb_e[NNZ];                // node ids grouped by edge
__device__ int   d_memb_n[NNZ];                // edge ids grouped by node

// ---------------------------------------------------------------------------
// 1. zero counters
// ---------------------------------------------------------------------------
__global__ void zero_cnt_kernel() {
    int idx = blockIdx.x * blockDim.x + threadIdx.x;
    int stride = gridDim.x * blockDim.x;
    for (int i = idx; i < N_EDGES; i += stride) d_cnt_e[i] = 0;
    for (int i = idx; i < N_NODES; i += stride) d_cnt_n[i] = 0;
}

// ---------------------------------------------------------------------------
// 2. histogram of both index arrays
// ---------------------------------------------------------------------------
__global__ void hist_kernel(const int* __restrict__ node_idx,
                            const int* __restrict__ edge_idx) {
    int idx = blockIdx.x * blockDim.x + threadIdx.x;
    int stride = gridDim.x * blockDim.x;
    for (int i = idx; i < NNZ; i += stride) {
        atomicAdd(&d_cnt_e[edge_idx[i]], 1);
        atomicAdd(&d_cnt_n[node_idx[i]], 1);
    }
}

// ---------------------------------------------------------------------------
// 3. exclusive scan of both count arrays (block 0 -> edges, block 1 -> nodes)
//    Also re-zeroes the count arrays (reused as rank counters in fill).
// ---------------------------------------------------------------------------
__global__ __launch_bounds__(1024)
void scan_two_kernel() {
    int* cnt;
    int* off;
    int  L;
    if (blockIdx.x == 0) { cnt = d_cnt_e; off = d_off_e; L = N_EDGES; }
    else                 { cnt = d_cnt_n; off = d_off_n; L = N_NODES; }

    const int tid  = threadIdx.x;
    const int lane = tid & 31;
    const int wid  = tid >> 5;
    __shared__ int warp_sum[32];

    int running = 0;
    for (int base = 0; base < L; base += 1024) {
        int i = base + tid;
        int v = (i < L) ? cnt[i] : 0;
        int orig = v;
        // warp inclusive scan
        #pragma unroll
        for (int d = 1; d < 32; d <<= 1) {
            int t = __shfl_up_sync(0xffffffffu, v, d);
            if (lane >= d) v += t;
        }
        if (lane == 31) warp_sum[wid] = v;
        __syncthreads();
        if (wid == 0) {
            int w = warp_sum[lane];
            #pragma unroll
            for (int d = 1; d < 32; d <<= 1) {
                int t = __shfl_up_sync(0xffffffffu, w, d);
                if (lane >= d) w += t;
            }
            warp_sum[lane] = w;
        }
        __syncthreads();
        int incl = v + (wid > 0 ? warp_sum[wid - 1] : 0);
        if (i < L) off[i + 1] = running + incl;
        int chunk_total = warp_sum[31];
        running += chunk_total;
        __syncthreads();   // protect warp_sum before next chunk
        (void)orig;
    }
    if (tid == 0) off[0] = 0;
    // re-zero counts for the fill pass
    for (int i = tid; i < L; i += 1024) cnt[i] = 0;
}

// ---------------------------------------------------------------------------
// 4. fill member lists (rank via int atomics)
// ---------------------------------------------------------------------------
__global__ void fill_kernel(const int* __restrict__ node_idx,
                            const int* __restrict__ edge_idx) {
    int idx = blockIdx.x * blockDim.x + threadIdx.x;
    int stride = gridDim.x * blockDim.x;
    for (int i = idx; i < NNZ; i += stride) {
        int n = node_idx[i];
        int e = edge_idx[i];
        int re = atomicAdd(&d_cnt_e[e], 1);
        d_memb_e[d_off_e[e] + re] = n;
        int rn = atomicAdd(&d_cnt_n[n], 1);
        d_memb_n[d_off_n[n] + rn] = e;
    }
}

// ---------------------------------------------------------------------------
// 5. reduce v2e: x1[e] = sum over member nodes of x0[n]   (no atomics)
//    one 64-thread block per edge; thread = one float4 channel group
// ---------------------------------------------------------------------------
__global__ __launch_bounds__(64)
void reduce_v2e(const float4* __restrict__ x0, float4* __restrict__ x1) {
    const int e   = blockIdx.x;
    const int tid = threadIdx.x;
    int beg = d_off_e[e];
    int end = d_off_e[e + 1];

    float4 s0 = make_float4(0.f, 0.f, 0.f, 0.f);
    float4 s1 = make_float4(0.f, 0.f, 0.f, 0.f);
    int j = beg;
    for (; j + 1 < end; j += 2) {
        int n0 = __ldg(&d_memb_e[j]);
        int n1 = __ldg(&d_memb_e[j + 1]);
        float4 v0 = __ldg(&x0[(size_t)n0 * C4 + tid]);
        float4 v1 = __ldg(&x0[(size_t)n1 * C4 + tid]);
        s0.x += v0.x; s0.y += v0.y; s0.z += v0.z; s0.w += v0.w;
        s1.x += v1.x; s1.y += v1.y; s1.z += v1.z; s1.w += v1.w;
    }
    if (j < end) {
        int n0 = __ldg(&d_memb_e[j]);
        float4 v0 = __ldg(&x0[(size_t)n0 * C4 + tid]);
        s0.x += v0.x; s0.y += v0.y; s0.z += v0.z; s0.w += v0.w;
    }
    s0.x += s1.x; s0.y += s1.y; s0.z += s1.z; s0.w += s1.w;
    x1[(size_t)e * C4 + tid] = s0;
}

// ---------------------------------------------------------------------------
// 6. reduce e2v (fused with +x0): g_m[n] = x0[n] + sum over incident edges x1[e]
// ---------------------------------------------------------------------------
__global__ __launch_bounds__(64)
void reduce_e2v(const float4* __restrict__ x0, const float4* __restrict__ x1) {
    const int n   = blockIdx.x;
    const int tid = threadIdx.x;
    int beg = d_off_n[n];
    int end = d_off_n[n + 1];

    float4 s0 = __ldg(&x0[(size_t)n * C4 + tid]);   // (1+eps)*x0, eps=0
    float4 s1 = make_float4(0.f, 0.f, 0.f, 0.f);
    int j = beg;
    for (; j + 1 < end; j += 2) {
        int e0 = __ldg(&d_memb_n[j]);
        int e1 = __ldg(&d_memb_n[j + 1]);
        float4 v0 = __ldg(&x1[(size_t)e0 * C4 + tid]);
        float4 v1 = __ldg(&x1[(size_t)e1 * C4 + tid]);
        s0.x += v0.x; s0.y += v0.y; s0.z += v0.z; s0.w += v0.w;
        s1.x += v1.x; s1.y += v1.y; s1.z += v1.z; s1.w += v1.w;
    }
    if (j < end) {
        int e0 = __ldg(&d_memb_n[j]);
        float4 v0 = __ldg(&x1[(size_t)e0 * C4 + tid]);
        s0.x += v0.x; s0.y += v0.y; s0.z += v0.z; s0.w += v0.w;
    }
    s0.x += s1.x; s0.y += s1.y; s0.z += s1.z; s0.w += s1.w;
    float4* m4 = reinterpret_cast<float4*>(g_m);
    m4[(size_t)n * C4 + tid] = s0;
}

// ---------------------------------------------------------------------------
// 7. GEMM: out0 = g_m @ W^T + b   via TF32 mma.sync  (g_m already = x0 + m)
// ---------------------------------------------------------------------------
#define GBM 64
#define GBN 256
#define GBK 16
#define SPAD 20

__device__ __forceinline__ uint32_t f2tf32(float f) {
    uint32_t r;
    asm("cvt.rna.tf32.f32 %0, %1;" : "=r"(r) : "f"(f));
    return r;
}

__device__ __forceinline__ void mma_tf32(float c[4], const uint32_t a[4], const uint32_t b[2]) {
    asm volatile(
        "mma.sync.aligned.m16n8k8.row.col.f32.tf32.tf32.f32 "
        "{%0,%1,%2,%3}, {%4,%5,%6,%7}, {%8,%9}, {%0,%1,%2,%3};\n"
        : "+f"(c[0]), "+f"(c[1]), "+f"(c[2]), "+f"(c[3])
        : "r"(a[0]), "r"(a[1]), "r"(a[2]), "r"(a[3]), "r"(b[0]), "r"(b[1]));
}

__global__ __launch_bounds__(256)
void gin_gemm_tf32(const float* __restrict__ W,
                   const float* __restrict__ bias,
                   float* __restrict__ out) {
    __shared__ uint32_t As[GBM][SPAD];
    __shared__ uint32_t Bs[GBN][SPAD];

    const int tid  = threadIdx.x;
    const int lane = tid & 31;
    const int wid  = tid >> 5;
    const int m_off = (wid >> 2) * 32;
    const int n_off = (wid & 3) * 64;
    const int m0 = blockIdx.x * GBM;

    const int a_row = tid >> 2;
    const int a_col = (tid & 3) * 4;
    const int  a_gm  = m0 + a_row;
    const bool a_ok  = a_gm < N_NODES;
    const size_t a_base = (size_t)a_gm * C + a_col;

    const int b_row = tid >> 1;
    const int b_col = (tid & 1) * 8;
    const size_t b_base = (size_t)b_row * C + b_col;

    float acc[2][8][4];
    #pragma unroll
    for (int mf = 0; mf < 2; mf++)
        #pragma unroll
        for (int nf = 0; nf < 8; nf++)
            #pragma unroll
            for (int q = 0; q < 4; q++)
                acc[mf][nf][q] = 0.f;

    float4 pa;
    float4 pb0, pb1, pb2, pb3;
    {
        pa = a_ok ? *reinterpret_cast<const float4*>(&g_m[a_base])
                  : make_float4(0.f, 0.f, 0.f, 0.f);
        pb0 = *reinterpret_cast<const float4*>(&W[b_base + 0]);
        pb1 = *reinterpret_cast<const float4*>(&W[b_base + 4]);
        pb2 = *reinterpret_cast<const float4*>(&W[b_base + (size_t)128 * C + 0]);
        pb3 = *reinterpret_cast<const float4*>(&W[b_base + (size_t)128 * C + 4]);
    }

    const int r  = lane >> 2;
    const int cq = lane & 3;

    for (int t = 0; t < C / GBK; t++) {
        As[a_row][a_col + 0] = f2tf32(pa.x);
        As[a_row][a_col + 1] = f2tf32(pa.y);
        As[a_row][a_col + 2] = f2tf32(pa.z);
        As[a_row][a_col + 3] = f2tf32(pa.w);

        Bs[b_row][b_col + 0] = f2tf32(pb0.x);
        Bs[b_row][b_col + 1] = f2tf32(pb0.y);
        Bs[b_row][b_col + 2] = f2tf32(pb0.z);
        Bs[b_row][b_col + 3] = f2tf32(pb0.w);
        Bs[b_row][b_col + 4] = f2tf32(pb1.x);
        Bs[b_row][b_col + 5] = f2tf32(pb1.y);
        Bs[b_row][b_col + 6] = f2tf32(pb1.z);
        Bs[b_row][b_col + 7] = f2tf32(pb1.w);
        Bs[b_row + 128][b_col + 0] = f2tf32(pb2.x);
        Bs[b_row + 128][b_col + 1] = f2tf32(pb2.y);
        Bs[b_row + 128][b_col + 2] = f2tf32(pb2.z);
        Bs[b_row + 128][b_col + 3] = f2tf32(pb2.w);
        Bs[b_row + 128][b_col + 4] = f2tf32(pb3.x);
        Bs[b_row + 128][b_col + 5] = f2tf32(pb3.y);
        Bs[b_row + 128][b_col + 6] = f2tf32(pb3.z);
        Bs[b_row + 128][b_col + 7] = f2tf32(pb3.w);
        __syncthreads();

        if (t + 1 < C / GBK) {
            int k0 = (t + 1) * GBK;
            if (a_ok) pa = *reinterpret_cast<const float4*>(&g_m[a_base + k0]);
            pb0 = *reinterpret_cast<const float4*>(&W[b_base + k0 + 0]);
            pb1 = *reinterpret_cast<const float4*>(&W[b_base + k0 + 4]);
            pb2 = *reinterpret_cast<const float4*>(&W[b_base + (size_t)128 * C + k0 + 0]);
            pb3 = *reinterpret_cast<const float4*>(&W[b_base + (size_t)128 * C + k0 + 4]);
        }

        #pragma unroll
        for (int ks = 0; ks < 2; ks++) {
            const int kk = ks * 8;
            uint32_t aF[2][4];
            #pragma unroll
            for (int mf = 0; mf < 2; mf++) {
                int row = m_off + mf * 16 + r;
                aF[mf][0] = As[row][kk + cq];
                aF[mf][1] = As[row + 8][kk + cq];
                aF[mf][2] = As[row][kk + cq + 4];
                aF[mf][3] = As[row + 8][kk + cq + 4];
            }
            #pragma unroll
            for (int nf = 0; nf < 8; nf++) {
                uint32_t bF[2];
                int col = n_off + nf * 8 + r;
                bF[0] = Bs[col][kk + cq];
                bF[1] = Bs[col][kk + cq + 4];
                mma_tf32(acc[0][nf], aF[0], bF);
                mma_tf32(acc[1][nf], aF[1], bF);
            }
        }
        __syncthreads();
    }

    #pragma unroll
    for (int mf = 0; mf < 2; mf++) {
        #pragma unroll
        for (int nf = 0; nf < 8; nf++) {
            int gc = n_off + nf * 8 + cq * 2;
            float bb0 = bias[gc];
            float bb1 = bias[gc + 1];
            int gr = m0 + m_off + mf * 16 + r;
            if (gr < N_NODES) {
                float2 v = make_float2(acc[mf][nf][0] + bb0, acc[mf][nf][1] + bb1);
                *reinterpret_cast<float2*>(&out[(size_t)gr * C + gc]) = v;
            }
            if (gr + 8 < N_NODES) {
                float2 v = make_float2(acc[mf][nf][2] + bb0, acc[mf][nf][3] + bb1);
                *reinterpret_cast<float2*>(&out[(size_t)(gr + 8) * C + gc]) = v;
            }
        }
    }
}

// ---------------------------------------------------------------------------
// Launch
// ---------------------------------------------------------------------------
extern "C" void kernel_launch(void* const* d_in, const int* in_sizes, int n_in,
                              void* d_out, int out_size) {
    const float* x0       = (const float*)d_in[0];
    const int*   node_idx = (const int*)d_in[1];
    const int*   edge_idx = (const int*)d_in[2];
    const float* W        = (const float*)d_in[3];
    const float* b        = (const float*)d_in[4];

    float* out = (float*)d_out;
    float* x1  = out + (size_t)N_NODES * C;

    // CSR build
    zero_cnt_kernel<<<256, 256>>>();
    hist_kernel<<<800, 256>>>(node_idx, edge_idx);
    scan_two_kernel<<<2, 1024>>>();
    fill_kernel<<<800, 256>>>(node_idx, edge_idx);

    // segment reductions (no float atomics)
    reduce_v2e<<<N_EDGES, 64>>>(reinterpret_cast<const float4*>(x0),
                                reinterpret_cast<float4*>(x1));
    reduce_e2v<<<N_NODES, 64>>>(reinterpret_cast<const float4*>(x0),
                                reinterpret_cast<const float4*>(x1));

    // GEMM: out0 = g_m @ W^T + b
    gin_gemm_tf32<<<(N_NODES + GBM - 1) / GBM, 256>>>(W, b, out);
}